// round 17
// baseline (speedup 1.0000x reference)
#include <cuda_runtime.h>
#include <cuda_bf16.h>

#define FULLMASK 0xffffffffu

// scratch (allocation-free contract: __device__ globals)
__device__ float g_s[16384];        // softmax logits, one per (b, c)
__device__ float g_hfsel[512*128];  // hf row at agent_id per b
__device__ float g_red[2];          // softmax max, sumexp

__device__ __forceinline__ float wredsum(float v){
  #pragma unroll
  for(int o=16;o;o>>=1) v += __shfl_xor_sync(FULLMASK,v,o);
  return v;
}

__device__ __forceinline__ unsigned smem_u32(const void* p){
  unsigned a;
  asm("{ .reg .u64 t; cvta.to.shared.u64 t, %1; cvt.u32.u64 %0, t; }" : "=r"(a) : "l"(p));
  return a;
}

// ---- warp-level bf16 MMA (baseline PTX, sm_80+; runs on tensor pipe) ----
__device__ __forceinline__ void mma16816(float* d, const unsigned* a, unsigned b0, unsigned b1){
  asm volatile("mma.sync.aligned.m16n8k16.row.col.f32.bf16.bf16.f32 "
    "{%0,%1,%2,%3}, {%4,%5,%6,%7}, {%8,%9}, {%0,%1,%2,%3};"
    : "+f"(d[0]),"+f"(d[1]),"+f"(d[2]),"+f"(d[3])
    : "r"(a[0]),"r"(a[1]),"r"(a[2]),"r"(a[3]), "r"(b0),"r"(b1));
}

// ---- ldmatrix/stmatrix (baseline PTX sm_75+/sm_90+) ----
__device__ __forceinline__ void ldsm4(unsigned* r, unsigned a){
  asm volatile("ldmatrix.sync.aligned.m8n8.x4.shared.b16 {%0,%1,%2,%3}, [%4];"
    : "=r"(r[0]),"=r"(r[1]),"=r"(r[2]),"=r"(r[3]) : "r"(a));
}
__device__ __forceinline__ void ldsm4t(unsigned* r, unsigned a){
  asm volatile("ldmatrix.sync.aligned.m8n8.x4.trans.shared.b16 {%0,%1,%2,%3}, [%4];"
    : "=r"(r[0]),"=r"(r[1]),"=r"(r[2]),"=r"(r[3]) : "r"(a));
}
__device__ __forceinline__ void stsm2(unsigned a, unsigned r0, unsigned r1){
  asm volatile("stmatrix.sync.aligned.m8n8.x2.shared.b16 [%0], {%1,%2};"
    :: "r"(a),"r"(r0),"r"(r1) : "memory");
}

// split x = hi + lo (both bf16), pack adjacent pairs (even elem low half)
__device__ __forceinline__ void splitpair(float a, float b, unsigned &hi, unsigned &lo){
  __nv_bfloat16 ha=__float2bfloat16_rn(a), hb=__float2bfloat16_rn(b);
  __nv_bfloat16 la=__float2bfloat16_rn(a-__bfloat162float(ha));
  __nv_bfloat16 lb=__float2bfloat16_rn(b-__bfloat162float(hb));
  hi=(unsigned)__bfloat16_as_ushort(ha)|((unsigned)__bfloat16_as_ushort(hb)<<16);
  lo=(unsigned)__bfloat16_as_ushort(la)|((unsigned)__bfloat16_as_ushort(lb)<<16);
}

// ---- smem byte layout ----
// W rows [n][k] bf16, stride 136 elems (272B) -> conflict-free frag loads.
// Bytes 256..271 of each act row (the stride pad) double as the cross-warp
// LN partial-sum exchange slots (never touched by ldmatrix/stmatrix).
#define B_WH2 0        // 34816  layer2 W hi
#define B_WL2 34816    // 34816  layer2 W lo
#define B_WH3 69632    // 34816  layer3 W hi
#define B_WL3 104448   // 34816  layer3 W lo
#define B_AH  139264   // 34816  act hi [e][k] (also: compaction scratch, final hacc)
#define B_AL  174080   // 34816  act lo       (also: xj preamble)
#define B_BASE 208896  // 16896  base[r][h] fp32 stride 132 (stage B: biases)
#define B_EL  225792   // 3072   e values (768 floats)
#define B_CL  228864   // 1536   (c<<5)|r shorts (768)
#define B_P1  230400   // 1536   w1row[128], ln1g[128], ln1b[128]
#define SMEM_BYTES 231936

__global__ __launch_bounds__(512,1)
void gnn_k1(const float* __restrict__ node_obs, const float* __restrict__ adj,
            const int* __restrict__ agent_id, const float* __restrict__ emb,
            const float* __restrict__ lin1_w, const float* __restrict__ lin1_b,
            const float* __restrict__ ln1_g, const float* __restrict__ ln1_b,
            const float* __restrict__ linh_w, const float* __restrict__ linh_b,
            const float* __restrict__ lnh_g, const float* __restrict__ lnh_b,
            const float* __restrict__ fc2a_w, const float* __restrict__ fc2a_b,
            const float* __restrict__ fc2b_w, const float* __restrict__ fc2b_b)
{
  extern __shared__ __align__(16) char smc[];
  const int b=blockIdx.x, t=threadIdx.x, lane=t&31, w=t>>5;
  const unsigned sbase = smem_u32(smc);

  int*   scount=(int*)(smc+B_AH);     // scratch aliases act_hi (pre-tile only)
  int*   sstart=scount+32;            // 33 entries
  short* clist=(short*)(smc+B_CL);
  float* elist=(float*)(smc+B_EL);
  float* sxj  =(float*)(smc+B_AL);    // alias, preamble only
  float* sbase_f=(float*)(smc+B_BASE);
  float* p1   =(float*)(smc+B_P1);

  // ---- weights fp32 -> split bf16 hi/lo, [n][k] stride 136 ----
  {
    const float4* src=(const float4*)linh_w;   // [l][k][n]
    for(int i=t;i<8192;i+=512){
      int l=i>>12, rem=i&4095, k=rem>>5, n0=(rem&31)*4;
      float4 v=src[i];
      char* dh=smc+(l?B_WH3:B_WH2);
      char* dl=smc+(l?B_WL3:B_WL2);
      float vv[4]={v.x,v.y,v.z,v.w};
      #pragma unroll
      for(int j=0;j<4;j++){
        unsigned off=(unsigned)(((n0+j)*136+k)*2);
        __nv_bfloat16 h=__float2bfloat16_rn(vv[j]);
        __nv_bfloat16 lo=__float2bfloat16_rn(vv[j]-__bfloat162float(h));
        *(__nv_bfloat16*)(dh+off)=h; *(__nv_bfloat16*)(dl+off)=lo;
      }
    }
  }
  if(t<128){ p1[t]=lin1_w[31*128+t]; p1[128+t]=ln1_g[t]; p1[256+t]=ln1_b[t]; }
  if(t<32){
    const int r=t;
    const float* no=node_obs+(size_t)b*512+r*16;
    #pragma unroll
    for(int k=0;k<15;k++) sxj[r*32+k]=no[k];
    int ent=(int)no[15];
    #pragma unroll
    for(int j=0;j<16;j++) sxj[r*32+15+j]=emb[ent*16+j];
    sxj[r*32+31]=0.f;
  }
  if(t<32) scount[t]=0;
  for(int i=t;i<768;i+=512){ clist[i]=-1; elist[i]=0.f; }
  __syncthreads();

  // ---- base[r][h] = xj[r] @ W1[0:31] + b1 (fp32, stride 132) ----
  {
    const int h=t&127, r0=t>>7;   // r0 in 0..3
    float acc[8];
    float bv=lin1_b[h];
    #pragma unroll
    for(int j=0;j<8;j++) acc[j]=bv;
    for(int k=0;k<31;k++){
      float wv=lin1_w[k*128+h];
      #pragma unroll
      for(int j=0;j<8;j++) acc[j]=fmaf(sxj[(r0+4*j)*32+k],wv,acc[j]);
    }
    #pragma unroll
    for(int j=0;j<8;j++) sbase_f[(r0+4*j)*132+h]=acc[j];
  }

  // ---- edge compaction (c-major): 2 edges/thread, c = t>>4 ----
  int nact;
  {
    const float* padj=adj+(size_t)b*1024;
    const int cc=t>>4;
    float ev[2]; int rv[2], av[2]; int cnt=0;
    #pragma unroll
    for(int q=0;q<2;q++){
      int idx=t*2+q, r=idx&31;
      float v=padj[r*32+cc];
      int a=(v>0.f)&&(v<1.0f);
      av[q]=a; ev[q]=v; rv[q]=r; cnt+=a;
    }
    if(cnt) atomicAdd(&scount[cc],cnt);
    int x=cnt;
    #pragma unroll
    for(int o=1;o<32;o<<=1){ int y=__shfl_up_sync(FULLMASK,x,o); if(lane>=o)x+=y; }
    __syncthreads();
    if(t==0){ int run=0;
      #pragma unroll
      for(int c=0;c<32;c++){ sstart[c]=run; run+=scount[c]; }
      sstart[32]=run;
    }
    __syncthreads();
    nact=sstart[32]; if(nact>768)nact=768;
    int pos=sstart[2*w]+x-cnt;
    #pragma unroll
    for(int q=0;q<2;q++){
      if(av[q]&&pos<768){ clist[pos]=(short)((cc<<5)|rv[q]); elist[pos]=ev[q]; pos++; }
    }
    __syncthreads();   // scratch (act area) now dead -> tiles may write act
  }

  const char* actH=smc+B_AH;
  const char* actL=smc+B_AL;
  const unsigned actHu=sbase+B_AH, actLu=sbase+B_AL;
  const int wp = w>>1;               // m-tile (16 edges), shared by warp pair
  const int nh = w&1;                // n half (64 cols)
  const int cb=(w&1)*16+(lane>>2);   // agg-mma c row
  const int colg=w>>1;               // agg column group (16 cols)
  const int col0=(lane&3)*2;

  // ---- per-lane ldmatrix/stmatrix address offsets ----
  const unsigned aOffA = (unsigned)((16*wp+(lane&15))*272 + (lane>>4)*16);
  const unsigned bOff  = (unsigned)((lane&7)*272 + (lane>>3)*16 + nh*17408);
  const unsigned sOff2 = (unsigned)((16*wp+(lane&15))*272 + nh*128);
  const unsigned gOff  = (unsigned)((lane&15)*272 + (colg*16 + (lane>>4)*8)*2);
  // cross-warp LN exchange slots (row pads): entry idx = wp*8 + quad
  const unsigned padW  = (unsigned)(((wp*8+(lane>>2))*2 + nh )*272 + 256);
  const unsigned padR  = (unsigned)(((wp*8+(lane>>2))*2 + (nh^1))*272 + 256);

  float hD[2][4];
  hD[0][0]=0;hD[0][1]=0;hD[0][2]=0;hD[0][3]=0;
  hD[1][0]=0;hD[1][1]=0;hD[1][2]=0;hD[1][3]=0;

  const int ntiles=(nact+127)>>7;
  for(int T=0;T<ntiles;T++){
    const int tb=T<<7;
    // ===== layer 1: 4 threads per edge (k quarters), LN, split -> act =====
    {
      const int el=8*w+(lane>>2);
      const int kq=lane&3;
      const int gi=tb+el;
      short cv=clist[gi];
      int r=cv&31; float e=elist[gi];
      const float4* brow=(const float4*)(sbase_f+r*132)+kq*8;
      const float4* w14=(const float4*)p1+kq*8;
      const float4* g14=(const float4*)(p1+128)+kq*8;
      const float4* b14=(const float4*)(p1+256)+kq*8;
      float s=0.f,p=0.f;
      #pragma unroll
      for(int q=0;q<8;q++){
        float4 bs=brow[q], wv=w14[q];
        float v0=fmaxf(fmaf(e,wv.x,bs.x),0.f);
        float v1=fmaxf(fmaf(e,wv.y,bs.y),0.f);
        float v2=fmaxf(fmaf(e,wv.z,bs.z),0.f);
        float v3=fmaxf(fmaf(e,wv.w,bs.w),0.f);
        s+=v0+v1+v2+v3;
        p=fmaf(v0,v0,fmaf(v1,v1,fmaf(v2,v2,fmaf(v3,v3,p))));
      }
      s+=__shfl_xor_sync(FULLMASK,s,1); p+=__shfl_xor_sync(FULLMASK,p,1);
      s+=__shfl_xor_sync(FULLMASK,s,2); p+=__shfl_xor_sync(FULLMASK,p,2);
      float mu=s*(1.f/128.f);
      float inv=rsqrtf(p*(1.f/128.f)-mu*mu+1e-5f);
      char* dh=(char*)actH+(el*136+kq*32)*2;
      char* dl=(char*)actL+(el*136+kq*32)*2;
      #pragma unroll
      for(int q=0;q<8;q++){
        float4 bs=brow[q], wv=w14[q], g=g14[q], bb=b14[q];
        float o0=(fmaxf(fmaf(e,wv.x,bs.x),0.f)-mu)*inv*g.x+bb.x;
        float o1=(fmaxf(fmaf(e,wv.y,bs.y),0.f)-mu)*inv*g.y+bb.y;
        float o2=(fmaxf(fmaf(e,wv.z,bs.z),0.f)-mu)*inv*g.z+bb.z;
        float o3=(fmaxf(fmaf(e,wv.w,bs.w),0.f)-mu)*inv*g.w+bb.w;
        unsigned h0,l0,h1,l1;
        splitpair(o0,o1,h0,l0); splitpair(o2,o3,h1,l1);
        *(uint2*)(dh+q*8)=make_uint2(h0,h1);
        *(uint2*)(dl+q*8)=make_uint2(l0,l1);
      }
    }
    __syncthreads();   // layer-1 writers != GEMM readers

    // ===== two hidden layers: warp tile = 16 edges x 64 cols =====
    #pragma unroll 1
    for(int l=0;l<2;l++){
      float d[8][4];
      #pragma unroll
      for(int n=0;n<8;n++){d[n][0]=0;d[n][1]=0;d[n][2]=0;d[n][3]=0;}
      const unsigned bBaseH = sbase + (l?B_WH3:B_WH2) + bOff;
      const unsigned bBaseL = sbase + (l?B_WL3:B_WL2) + bOff;
      #pragma unroll 1
      for(int kk2=0;kk2<4;kk2++){
        unsigned Ah0[4],Ah1[4],Al0[4],Al1[4];
        ldsm4(Ah0, actHu + aOffA + (2*kk2  )*32);
        ldsm4(Ah1, actHu + aOffA + (2*kk2+1)*32);
        ldsm4(Al0, actLu + aOffA + (2*kk2  )*32);
        ldsm4(Al1, actLu + aOffA + (2*kk2+1)*32);
        unsigned bh[2][4], bl[2][4];
        ldsm4(bh[0], bBaseH + kk2*64);
        ldsm4(bl[0], bBaseL + kk2*64);
        #pragma unroll
        for(int nt=0;nt<8;nt++){
          const int cur=nt&1, nxt=cur^1;
          if(nt<7){
            ldsm4(bh[nxt], bBaseH + (nt+1)*2176 + kk2*64);
            ldsm4(bl[nxt], bBaseL + (nt+1)*2176 + kk2*64);
          }
          mma16816(d[nt],Ah0,bh[cur][0],bh[cur][1]);
          mma16816(d[nt],Al0,bh[cur][0],bh[cur][1]);
          mma16816(d[nt],Ah0,bl[cur][0],bl[cur][1]);
          mma16816(d[nt],Ah1,bh[cur][2],bh[cur][3]);
          mma16816(d[nt],Al1,bh[cur][2],bh[cur][3]);
          mma16816(d[nt],Ah1,bl[cur][2],bl[cur][3]);
        }
      }
      // epilogue: bias+relu, per-row partial sums over this warp's 64 cols
      const float* lhbg=linh_b+l*128+nh*64;
      float2 bias[8];
      #pragma unroll
      for(int n=0;n<8;n++) bias[n]=*(const float2*)(lhbg+n*8+col0);
      float s0=0,p0=0,s1=0,q1=0;
      #pragma unroll
      for(int n=0;n<8;n++){
        float v0=fmaxf(d[n][0]+bias[n].x,0.f);
        float v1=fmaxf(d[n][1]+bias[n].y,0.f);
        float v2=fmaxf(d[n][2]+bias[n].x,0.f);
        float v3=fmaxf(d[n][3]+bias[n].y,0.f);
        s0+=v0+v1; p0=fmaf(v0,v0,fmaf(v1,v1,p0));
        s1+=v2+v3; q1=fmaf(v2,v2,fmaf(v3,v3,q1));
      }
      #pragma unroll
      for(int o=1;o<4;o<<=1){
        s0+=__shfl_xor_sync(FULLMASK,s0,o);
        p0+=__shfl_xor_sync(FULLMASK,p0,o);
        s1+=__shfl_xor_sync(FULLMASK,s1,o);
        q1+=__shfl_xor_sync(FULLMASK,q1,o);
      }
      // exchange with partner warp via act-row pad slots
      if((lane&3)==0){
        float4 v4; v4.x=s0; v4.y=p0; v4.z=s1; v4.w=q1;
        *(float4*)(smc + B_AH + padW) = v4;
      }
      __syncthreads();
      {
        float4 o4 = *(const float4*)(smc + B_AH + padR);
        s0+=o4.x; p0+=o4.y; s1+=o4.z; q1+=o4.w;
      }
      float mu0=s0*(1.f/128.f), inv0=rsqrtf(p0*(1.f/128.f)-mu0*mu0+1e-5f);
      float mu1=s1*(1.f/128.f), inv1=rsqrtf(q1*(1.f/128.f)-mu1*mu1+1e-5f);
      const float* gg=lnh_g+l*128+nh*64;
      const float* b2g=lnh_b+l*128+nh*64;
      #pragma unroll
      for(int n=0;n<8;n++){
        float2 g=*(const float2*)(gg+n*8+col0);
        float2 b2=*(const float2*)(b2g+n*8+col0);
        float o0=(fmaxf(d[n][0]+bias[n].x,0.f)-mu0)*inv0*g.x+b2.x;
        float o1=(fmaxf(d[n][1]+bias[n].y,0.f)-mu0)*inv0*g.y+b2.y;
        float o2=(fmaxf(d[n][2]+bias[n].x,0.f)-mu1)*inv1*g.x+b2.x;
        float o3=(fmaxf(d[n][3]+bias[n].y,0.f)-mu1)*inv1*g.y+b2.y;
        unsigned h0,l0,h1,l1;
        splitpair(o0,o1,h0,l0); splitpair(o2,o3,h1,l1);
        stsm2(actHu + sOff2 + n*16, h0,h1);
        stsm2(actLu + sOff2 + n*16, l0,l1);
      }
      __syncthreads();   // stores visible to next layer / agg
    }

    // ===== aggregation: h += sel(c,e) @ m via MMA (sel exact 0/1) =====
    #pragma unroll 1
    for(int kk=0;kk<8;kk++){
      int e0=tb+kk*16+col0;   // global index into clist
      int c0v=clist[e0]>>5, c1v=clist[e0+1]>>5;
      int c2v=clist[e0+8]>>5, c3v=clist[e0+9]>>5;
      unsigned A[4];
      A[0]=(c0v==cb  ?0x3F80u:0u)|((c1v==cb  )?0x3F800000u:0u);
      A[1]=(c0v==cb+8?0x3F80u:0u)|((c1v==cb+8)?0x3F800000u:0u);
      A[2]=(c2v==cb  ?0x3F80u:0u)|((c3v==cb  )?0x3F800000u:0u);
      A[3]=(c2v==cb+8?0x3F80u:0u)|((c3v==cb+8)?0x3F800000u:0u);
      unsigned bhA[4], blA[4];
      ldsm4t(bhA, actHu + gOff + kk*4352);
      ldsm4t(blA, actLu + gOff + kk*4352);
      mma16816(hD[0],A,bhA[0],bhA[1]); mma16816(hD[0],A,blA[0],blA[1]);
      mma16816(hD[1],A,bhA[2],bhA[3]); mma16816(hD[1],A,blA[2],blA[3]);
    }
    __syncthreads();   // agg reads done before next tile's layer-1 writes
  }

  // ---- write h to smem (act region dead) ----
  float* hacc=(float*)(smc+B_AH);
  __syncthreads();
  #pragma unroll
  for(int j=0;j<2;j++){
    int col=colg*16+j*8+col0;
    hacc[cb*132+col]  =hD[j][0];
    hacc[cb*132+col+1]=hD[j][1];
    hacc[(cb+8)*132+col]  =hD[j][2];
    hacc[(cb+8)*132+col+1]=hD[j][3];
  }
  __syncthreads();

  // ---- stage B: s[b,c] = relu(h @ fc2a + b2a) @ fc2b + b2b ----
  float* w2s=(float*)(smc+B_WH2);
  {
    const float4* s2=(const float4*)fc2a_w; float4* d2=(float4*)w2s;
    for(int i=t;i<4096;i+=512) d2[i]=s2[i];
    float* bb=(float*)(smc+B_BASE);
    if(t<128){ bb[t]=fc2a_b[t]; bb[128+t]=fc2b_w[t]; }
  }
  __syncthreads();
  {
    const float* bb=(const float*)(smc+B_BASE);
    float4 b2=((const float4*)bb)[lane];
    float4 f2=((const float4*)(bb+128))[lane];
    float acc[2][4];
    #pragma unroll
    for(int cc=0;cc<2;cc++){acc[cc][0]=b2.x;acc[cc][1]=b2.y;acc[cc][2]=b2.z;acc[cc][3]=b2.w;}
    const int c0=w*2;
    #pragma unroll 4
    for(int k=0;k<128;k++){
      float4 wv=((const float4*)w2s)[k*32+lane];
      #pragma unroll
      for(int cc=0;cc<2;cc++){
        float a=hacc[(c0+cc)*132+k];
        acc[cc][0]=fmaf(a,wv.x,acc[cc][0]);
        acc[cc][1]=fmaf(a,wv.y,acc[cc][1]);
        acc[cc][2]=fmaf(a,wv.z,acc[cc][2]);
        acc[cc][3]=fmaf(a,wv.w,acc[cc][3]);
      }
    }
    float b2b=fc2b_b[0];
    #pragma unroll
    for(int cc=0;cc<2;cc++){
      float p=fmaxf(acc[cc][0],0.f)*f2.x+fmaxf(acc[cc][1],0.f)*f2.y
             +fmaxf(acc[cc][2],0.f)*f2.z+fmaxf(acc[cc][3],0.f)*f2.w;
      p=wredsum(p);
      if(lane==0) g_s[b*32+c0+cc]=p+b2b;
    }
  }
  if(t<128){
    int ag=agent_id[b];
    g_hfsel[b*128+t]=hacc[ag*132+t];
  }
}

// ---- global softmax reduction over 16384 logits ----
__global__ void gnn_k2(){
  __shared__ float sw[8];
  int t=threadIdx.x, lane=t&31, w=t>>5;
  float m=-3.4e38f;
  for(int i=t;i<16384;i+=256) m=fmaxf(m,g_s[i]);
  #pragma unroll
  for(int o=16;o;o>>=1) m=fmaxf(m,__shfl_xor_sync(FULLMASK,m,o));
  if(lane==0) sw[w]=m;
  __syncthreads();
  float M=sw[0];
  #pragma unroll
  for(int i=1;i<8;i++) M=fmaxf(M,sw[i]);
  float acc=0.f;
  for(int i=t;i<16384;i+=256) acc+=expf(g_s[i]-M);
  acc=wredsum(acc);
  __syncthreads();
  if(lane==0) sw[w]=acc;
  __syncthreads();
  if(t==0){
    float S=0.f;
    #pragma unroll
    for(int i=0;i<8;i++) S+=sw[i];
    g_red[0]=M; g_red[1]=S;
  }
}

// ---- per-b head on the single selected row ----
__global__ __launch_bounds__(128)
void gnn_k3(const float* __restrict__ fc3_w, const float* __restrict__ fc3_b,
            const float* __restrict__ ln3_g, const float* __restrict__ ln3_b,
            const float* __restrict__ fc4_w, const float* __restrict__ fc4_b,
            const float* __restrict__ ln4_g, const float* __restrict__ ln4_b,
            const int* __restrict__ agent_id, float* __restrict__ out)
{
  __shared__ float shf[128], sy[128], sred[8];
  int b=blockIdx.x, t=threadIdx.x, lane=t&31, w=t>>5;
  shf[t]=g_hfsel[b*128+t];
  __syncthreads();
  float acc=fc3_b[t];
  #pragma unroll 4
  for(int k=0;k<128;k++) acc=fmaf(shf[k],fc3_w[k*128+t],acc);
  float v=fmaxf(acc,0.f);
  float s1=wredsum(v), s2=wredsum(v*v);
  if(lane==0){sred[w]=s1; sred[4+w]=s2;}
  __syncthreads();
  s1=sred[0]+sred[1]+sred[2]+sred[3];
  s2=sred[4]+sred[5]+sred[6]+sred[7];
  float mu=s1*(1.f/128.f);
  float inv=rsqrtf(s2*(1.f/128.f)-mu*mu+1e-5f);
  float vn=(v-mu)*inv*ln3_g[t]+ln3_b[t];
  int ag=agent_id[b];
  float alpha=expf(g_s[b*32+ag]-g_red[0])/g_red[1];
  sy[t]=alpha*vn;
  __syncthreads();
  acc=fc4_b[t];
  #pragma unroll 4
  for(int k=0;k<128;k++) acc=fmaf(sy[k],fc4_w[k*128+t],acc);
  v=fmaxf(acc,0.f);
  s1=wredsum(v); s2=wredsum(v*v);
  __syncthreads();
  if(lane==0){sred[w]=s1; sred[4+w]=s2;}
  __syncthreads();
  s1=sred[0]+sred[1]+sred[2]+sred[3];
  s2=sred[4]+sred[5]+sred[6]+sred[7];
  mu=s1*(1.f/128.f);
  inv=rsqrtf(s2*(1.f/128.f)-mu*mu+1e-5f);
  out[b*128+t]=(v-mu)*inv*ln4_g[t]+ln4_b[t];
}

extern "C" void kernel_launch(void* const* d_in, const int* in_sizes, int n_in,
                              void* d_out, int out_size)
{
  const float* node_obs=(const float*)d_in[0];
  const float* adj     =(const float*)d_in[1];
  const int*   agent_id=(const int*)  d_in[2];
  const float* emb     =(const float*)d_in[3];
  const float* lin1_w  =(const float*)d_in[4];
  const float* lin1_b  =(const float*)d_in[5];
  const float* ln1_g   =(const float*)d_in[6];
  const float* ln1_b   =(const float*)d_in[7];
  const float* linh_w  =(const float*)d_in[8];
  const float* linh_b  =(const float*)d_in[9];
  const float* lnh_g   =(const float*)d_in[10];
  const float* lnh_b   =(const float*)d_in[11];
  const float* fc2a_w  =(const float*)d_in[12];
  const float* fc2a_b  =(const float*)d_in[13];
  const float* fc2b_w  =(const float*)d_in[14];
  const float* fc2b_b  =(const float*)d_in[15];
  const float* fc3_w   =(const float*)d_in[16];
  const float* fc3_b   =(const float*)d_in[17];
  const float* ln3_g   =(const float*)d_in[18];
  const float* ln3_b   =(const float*)d_in[19];
  const float* fc4_w   =(const float*)d_in[20];
  const float* fc4_b   =(const float*)d_in[21];
  const float* ln4_g   =(const float*)d_in[22];
  const float* ln4_b   =(const float*)d_in[23];

  cudaFuncSetAttribute(gnn_k1, cudaFuncAttributeMaxDynamicSharedMemorySize, SMEM_BYTES);

  gnn_k1<<<512,512,SMEM_BYTES>>>(node_obs,adj,agent_id,emb,
                                 lin1_w,lin1_b,ln1_g,ln1_b,
                                 linh_w,linh_b,lnh_g,lnh_b,
                                 fc2a_w,fc2a_b,fc2b_w,fc2b_b);
  gnn_k2<<<1,256>>>();
  gnn_k3<<<512,128>>>(fc3_w,fc3_b,ln3_g,ln3_b,fc4_w,fc4_b,ln4_g,ln4_b,
                      agent_id,(float*)d_out);
}